// round 17
// baseline (speedup 1.0000x reference)
#include <cuda_runtime.h>

// Fixed problem shape: B=16, C=1, H=128, W=8192, NMAX=64
#define BB   16
#define HH   128
#define WW   8192
#define NMX  64
#define ROWS 16                // rows per block -> grid.z = 8, 1024 blocks
#define BIGV 0x3FFFFFFF

// ---------------------------------------------------------------------------
// SINGLE fused kernel: meta scan + cheap classification + warp-private
// transpose pack. grid = (WW/1024=8, BB=16, HH/16=8) = 1024 blocks (single
// wave at 8 blocks/SM), block 256 = 8 warps.
//
// Preamble: 64-wide shuffle scan of chirp widths -> compressed starts/ends in
// shared; then ONE binary search per lane + linear advance (segments are
// contiguous with extent >= 21, stride-32 columns advance cur by <= 2).
// Block (0,b,0) writes xi_new.
//
// Hot loop (per warp, NO block barriers): each warp owns a 128-col swath +
// private smem slice. 2-row pipeline: 8 coalesced LDG.32 (1 wavefront each)
// -> STS conflict-free -> __syncwarp -> LDS.128 -> coalesced STG.128.
// ---------------------------------------------------------------------------
__global__ void __launch_bounds__(256)
pack_kernel(const float* __restrict__ x,
            const int*   __restrict__ xi,
            const int*   __restrict__ N,
            const float* __restrict__ sep_param,
            float* __restrict__ out,
            float* __restrict__ out_xi,
            int write_xi) {
    const int b    = blockIdx.y;
    const int t    = threadIdx.x;
    const int w    = t >> 5;
    const int lane = t & 31;

    __shared__ __align__(16) float s_tile[8][2][128];  // 8 KB warp-private
    __shared__ int s_start[NMX + 1];
    __shared__ int s_end[NMX];
    __shared__ int s_src[NMX];
    __shared__ int s_n;
    __shared__ int sh_w0;

    // ---------------- meta scan (2 block syncs) -----------------------
    if (t == 0) s_n = N[b];
    __syncthreads();
    const int n = s_n;

    if (t < NMX) {
        const int s = xi[(b * NMX + t) * 2 + 0];
        const int e = xi[(b * NMX + t) * 2 + 1];
        const int valid = (t < n) ? 1 : 0;
        const int wv = valid ? max(e - s, 0) : 0;

        int sc = wv;
        #pragma unroll
        for (int off = 1; off < 32; off <<= 1) {
            int v = __shfl_up_sync(0xFFFFFFFFu, sc, off);
            if ((t & 31) >= off) sc += v;
        }
        if (t == 31) sh_w0 = sc;
        __syncwarp();
        s_end[t]   = sc;      // stash partial scan
        s_src[t]   = s;
        s_start[t] = valid;   // stash validity
    }
    __syncthreads();
    if (t < NMX) {
        const int valid = s_start[t];
        const int s = s_src[t];
        const int e = xi[(b * NMX + t) * 2 + 1];
        const int wv = valid ? max(e - s, 0) : 0;
        const int csum = s_end[t] + ((t >= 32) ? sh_w0 : 0);
        const int sn = csum - wv + t;
        const int en = csum + t;
        s_start[t] = valid ? sn : BIGV;
        s_end[t]   = en;
        if (write_xi && blockIdx.x == 0 && blockIdx.z == 0) {
            out_xi[(b * NMX + t) * 2 + 0] = valid ? (float)sn : 0.0f;
            out_xi[(b * NMX + t) * 2 + 1] = valid ? (float)en : 0.0f;
        }
    }
    if (t == 0) s_start[NMX] = BIGV;
    __syncthreads();

    // ------ classification: 1 search + linear advance (stride-32 cols) ----
    const int   wcol = blockIdx.x * 1024 + w * 128;
    const float sep  = sep_param[0];

    int   mm[4];
    float fv[4];
    {
        const int jbase = wcol + lane;
        int lo = 0, hi = n;
        while (lo < hi) {
            int mid = (lo + hi) >> 1;
            if (s_start[mid] <= jbase) lo = mid + 1; else hi = mid;
        }
        int cur = lo - 1;
        #pragma unroll
        for (int k = 0; k < 4; k++) {
            const int j = jbase + 32 * k;
            while (j >= s_start[cur + 1]) cur++;   // <= 2 steps (extent >= 21)
            const int s = s_start[cur];
            const int e = s_end[cur];
            int   o = -1;
            float f = 0.0f;
            if (j < e)                      o = s_src[cur] + (j - s);
            else if (j == e && cur < n - 1) f = sep;
            mm[k] = o;
            fv[k] = f;
        }
    }

    // ---------------- hot loop: warp-private transpose pack ----------
    const int h0 = blockIdx.z * ROWS;
    const float* __restrict__ xb = x   + (size_t)b * HH * WW + (size_t)h0 * WW;
    float* __restrict__       ob = out + (size_t)b * HH * WW + (size_t)h0 * WW;

    #pragma unroll 4
    for (int r = 0; r < ROWS; r += 2) {
        // coalesced gather: 8 independent LDGs (2 rows x 4 chunks)
        float v[2][4];
        #pragma unroll
        for (int rr = 0; rr < 2; rr++) {
            const size_t row = (size_t)(r + rr) * WW;
            #pragma unroll
            for (int k = 0; k < 4; k++)
                v[rr][k] = (mm[k] >= 0) ? __ldg(xb + row + mm[k]) : fv[k];
        }
        // stage in warp-private smem (conflict-free STS)
        #pragma unroll
        for (int rr = 0; rr < 2; rr++)
            #pragma unroll
            for (int k = 0; k < 4; k++)
                s_tile[w][rr][lane + 32 * k] = v[rr][k];
        __syncwarp();
        // read back as float4, coalesced STG.128
        #pragma unroll
        for (int rr = 0; rr < 2; rr++) {
            const float4 f = *reinterpret_cast<const float4*>(
                &s_tile[w][rr][4 * lane]);
            __stcs(reinterpret_cast<float4*>(
                ob + (size_t)(r + rr) * WW + wcol + 4 * lane), f);
        }
        __syncwarp();   // slices reused next iteration
    }
}

// ---------------------------------------------------------------------------
extern "C" void kernel_launch(void* const* d_in, const int* in_sizes, int n_in,
                              void* d_out, int out_size) {
    const float* x   = (const float*)d_in[0];
    const int*   xi  = (const int*)  d_in[1];
    const int*   N   = (const int*)  d_in[2];
    const float* sep = (const float*)d_in[3];
    float*       out = (float*)d_out;

    const long long XN = (long long)BB * HH * WW;   // 16,777,216
    const int write_xi = ((long long)out_size > XN) ? 1 : 0;

    dim3 grid(WW / 1024, BB, HH / ROWS);
    pack_kernel<<<grid, 256>>>(x, xi, N, sep, out, out + XN, write_xi);
}